// round 13
// baseline (speedup 1.0000x reference)
#include <cuda_runtime.h>
#include <cuda_bf16.h>
#include <math.h>
#include <stdint.h>

#define NTOK 32768        // B*T
#define HD   160          // hidden = embed
#define NV   16           // variables
#define TA   64           // stage A + B token tile
#define PA2  84           // packed-A pitch (u32)  -> conflict-free
#define PB2  168          // packed-B pitch (u32)  -> conflict-free
#define CHUNK_U32 (2*16*PB2)   // 5376 u32: hi tile [16][168] then lo tile
#define PAB  20           // stage B big-A pitch (u32)
#define PBB  200          // stage B big-B pitch (u32)
#define CHUNKB 6400       // u32 per big-B chunk (hi 3200 + lo 3200)

static __device__ float g_embt[(size_t)NTOK * HD * NV];  // emb transposed [n][v][e]
static __device__ float g_ctx[64 * HD];
static __device__ __align__(16) uint32_t g_trh[(size_t)NTOK * NV * 80];
static __device__ __align__(16) uint32_t g_trl[(size_t)NTOK * NV * 80];
static __device__ __align__(16) uint32_t g_wsplA[(size_t)16 * 4 * 5 * CHUNK_U32];
static __device__ __align__(16) uint32_t g_wsplB1[(size_t)80 * CHUNKB];
static __device__ __align__(16) uint32_t g_wsplB2[(size_t)5 * CHUNK_U32];

__device__ __forceinline__ float eluf(float x) { return x > 0.f ? x : expm1f(x); }
__device__ __forceinline__ float sigf(float x) { return 1.f / (1.f + expf(-x)); }

__device__ __forceinline__ uint32_t smem_u32(const void* p) {
    uint32_t a;
    asm("{ .reg .u64 t; cvta.to.shared.u64 t, %1; cvt.u32.u64 %0, t; }" : "=r"(a) : "l"(p));
    return a;
}
__device__ __forceinline__ void cp16(uint32_t saddr, const uint32_t* g) {
    asm volatile("cp.async.cg.shared.global [%0], [%1], 16;" :: "r"(saddr), "l"(g));
}
#define CP_COMMIT() asm volatile("cp.async.commit_group;" ::: "memory")
#define CP_WAIT1()  asm volatile("cp.async.wait_group 1;" ::: "memory")
#define CP_WAIT0()  asm volatile("cp.async.wait_group 0;" ::: "memory")

__device__ __forceinline__ void mma16(float* c, const uint32_t* a, const uint32_t* b) {
    asm volatile("mma.sync.aligned.m16n8k16.row.col.f32.bf16.bf16.f32 "
        "{%0,%1,%2,%3}, {%4,%5,%6,%7}, {%8,%9}, {%0,%1,%2,%3};"
        : "+f"(c[0]), "+f"(c[1]), "+f"(c[2]), "+f"(c[3])
        : "r"(a[0]), "r"(a[1]), "r"(a[2]), "r"(a[3]), "r"(b[0]), "r"(b[1]));
}

__device__ __forceinline__ void splitpack(float v0, float v1, uint32_t& hi, uint32_t& lo) {
    __nv_bfloat16 h0 = __float2bfloat16(v0), h1 = __float2bfloat16(v1);
    __nv_bfloat16 l0 = __float2bfloat16(v0 - __bfloat162float(h0));
    __nv_bfloat16 l1 = __float2bfloat16(v1 - __bfloat162float(h1));
    __nv_bfloat162 hh; hh.x = h0; hh.y = h1;
    __nv_bfloat162 ll; ll.x = l0; ll.y = l1;
    hi = *reinterpret_cast<uint32_t*>(&hh);
    lo = *reinterpret_cast<uint32_t*>(&ll);
}
__device__ __forceinline__ float2 unpk(uint32_t hi, uint32_t lo) {
    __nv_bfloat162 h = *reinterpret_cast<__nv_bfloat162*>(&hi);
    __nv_bfloat162 l = *reinterpret_cast<__nv_bfloat162*>(&lo);
    float2 r;
    r.x = __bfloat162float(h.x) + __bfloat162float(l.x);
    r.y = __bfloat162float(h.y) + __bfloat162float(l.y);
    return r;
}

// ===================== prep kernels (unchanged) =====================
__global__ void __launch_bounds__(256) prepA_kernel(
    const float* __restrict__ W1, const float* __restrict__ W2,
    const float* __restrict__ Wg, const float* __restrict__ Wv)
{
    int b = blockIdx.x;
    int c = b % 5, mat = (b / 5) & 3, v = b / 20;
    const float* W = (mat == 0 ? W1 : mat == 1 ? W2 : mat == 2 ? Wg : Wv) + (size_t)v * HD * HD;
    uint32_t* dst = g_wsplA + (size_t)b * CHUNK_U32;
    for (int i = threadIdx.x; i < 16 * PB2; i += 256) {
        int pr = i / PB2, col = i - pr * PB2;
        float w0 = 0.f, w1 = 0.f;
        if (col < HD) {
            int k0 = c * 32 + 2 * pr;
            w0 = W[(size_t)k0 * HD + col];
            w1 = W[(size_t)(k0 + 1) * HD + col];
        }
        uint32_t hi, lo;
        splitpack(w0, w1, hi, lo);
        dst[i] = hi;
        dst[16 * PB2 + i] = lo;
    }
}

__global__ void __launch_bounds__(256) prepB1_kernel(
    const float* __restrict__ W1, const float* __restrict__ Wsk)
{
    int c = blockIdx.x;
    uint32_t* dst = g_wsplB1 + (size_t)c * CHUNKB;
    for (int i = threadIdx.x; i < 16 * PBB; i += 256) {
        int pr = i / PBB, col = i - pr * PBB;
        int k0 = c * 32 + 2 * pr, k1 = k0 + 1;
        int pk0 = (k0 % HD) * NV + (k0 / HD);
        int pk1 = (k1 % HD) * NV + (k1 / HD);
        float w0 = 0.f, w1 = 0.f;
        if (col < HD) {
            w0 = W1[(size_t)pk0 * HD + col];
            w1 = W1[(size_t)pk1 * HD + col];
        } else if (col < HD + NV) {
            w0 = Wsk[(size_t)pk0 * NV + (col - HD)];
            w1 = Wsk[(size_t)pk1 * NV + (col - HD)];
        }
        uint32_t hi, lo;
        splitpack(w0, w1, hi, lo);
        dst[i] = hi;
        dst[16 * PBB + i] = lo;
    }
}

__global__ void __launch_bounds__(256) prepB2_kernel(const float* __restrict__ W2) {
    int c = blockIdx.x;
    uint32_t* dst = g_wsplB2 + (size_t)c * CHUNK_U32;
    for (int i = threadIdx.x; i < 16 * PB2; i += 256) {
        int pr = i / PB2, col = i - pr * PB2;
        float w0 = 0.f, w1 = 0.f;
        if (col < HD) {
            int k0 = c * 32 + 2 * pr;
            w0 = W2[(size_t)k0 * HD + col];
            w1 = W2[(size_t)(k0 + 1) * HD + col];
        }
        uint32_t hi, lo;
        splitpack(w0, w1, hi, lo);
        dst[i] = hi;
        dst[16 * PB2 + i] = lo;
    }
}

// ===================== shared mma machinery =====================
extern __shared__ float smem[];

// stage one CHUNK_U32 (1344 cp16) with 256 threads
__device__ __forceinline__ void stage_chunk256(uint32_t* sdst, const uint32_t* __restrict__ g, int tid) {
    uint32_t s = smem_u32(sdst);
#pragma unroll
    for (int i = 0; i < 5; ++i) {
        int q = i * 256 + tid;
        cp16(s + q * 16, g + q * 4);
    }
    int q = 1280 + tid;
    if (q < 1344) cp16(s + q * 16, g + q * 4);
}
// same with 512 threads
__device__ __forceinline__ void stage_chunk512(uint32_t* sdst, const uint32_t* __restrict__ g, int tid) {
    uint32_t s = smem_u32(sdst);
#pragma unroll
    for (int i = 0; i < 2; ++i) {
        int q = i * 512 + tid;
        cp16(s + q * 16, g + q * 4);
    }
    int q = 1024 + tid;
    if (q < 1344) cp16(s + q * 16, g + q * 4);
}

__device__ __forceinline__ void loadB(const uint32_t* Bh, const uint32_t* Bl, int s,
                                      uint32_t bh[5][2], uint32_t bl[5][2],
                                      int g, int t, int n0w) {
#pragma unroll
    for (int f = 0; f < 5; ++f) {
        int nn = n0w + f * 8 + g;
        bh[f][0] = Bh[(s * 8 + t) * PB2 + nn];
        bh[f][1] = Bh[(s * 8 + 4 + t) * PB2 + nn];
        bl[f][0] = Bl[(s * 8 + t) * PB2 + nn];
        bl[f][1] = Bl[(s * 8 + 4 + t) * PB2 + nn];
    }
}

__device__ __forceinline__ void loadA32(const uint32_t* s_Ah2, const uint32_t* s_Al2, int kp,
                                        uint32_t ah[2][4], uint32_t al[2][4],
                                        int g, int t, int m0w) {
#pragma unroll
    for (int mf = 0; mf < 2; ++mf) {
        int r0 = (m0w + mf * 16 + g) * PA2;
        int r1 = r0 + 8 * PA2;
        ah[mf][0] = s_Ah2[r0 + kp + t];     ah[mf][1] = s_Ah2[r1 + kp + t];
        ah[mf][2] = s_Ah2[r0 + kp + 4 + t]; ah[mf][3] = s_Ah2[r1 + kp + 4 + t];
        al[mf][0] = s_Al2[r0 + kp + t];     al[mf][1] = s_Al2[r1 + kp + t];
        al[mf][2] = s_Al2[r0 + kp + 4 + t]; al[mf][3] = s_Al2[r1 + kp + 4 + t];
    }
}

__device__ __forceinline__ void loadA16(const uint32_t* Ah, const uint32_t* Al, int pitch, int kp,
                                        uint32_t ah[4], uint32_t al[4], int g, int t, int m0w) {
    int r0 = (m0w + g) * pitch;
    int r1 = r0 + 8 * pitch;
    ah[0] = Ah[r0 + kp + t];     ah[1] = Ah[r1 + kp + t];
    ah[2] = Ah[r0 + kp + 4 + t]; ah[3] = Ah[r1 + kp + 4 + t];
    al[0] = Al[r0 + kp + t];     al[1] = Al[r1 + kp + t];
    al[2] = Al[r0 + kp + 4 + t]; al[3] = Al[r1 + kp + 4 + t];
}

#define MMA_T5x2(acc, A, B) \
    _Pragma("unroll") for (int f_ = 0; f_ < 5; ++f_) \
    _Pragma("unroll") for (int mf_ = 0; mf_ < 2; ++mf_) \
        mma16(acc[f_][mf_], (A)[mf_], (B)[f_]);
#define MMA_T5(acc, A, B) \
    _Pragma("unroll") for (int f_ = 0; f_ < 5; ++f_) \
        mma16(acc[f_], (A), (B)[f_]);
#define MMA_T6(acc, A, B) \
    _Pragma("unroll") for (int f_ = 0; f_ < 6; ++f_) \
        mma16(acc[f_], (A), (B)[f_]);

// 32-row x 40-col chunk (stage A)
__device__ __forceinline__ void mma_chunk32(const uint32_t* sB, float acc[5][2][4],
                                            const uint32_t* s_Ah2, const uint32_t* s_Al2,
                                            int kp0, int g, int t, int m0w, int n0w) {
    const uint32_t* Bh = sB;
    const uint32_t* Bl = sB + 16 * PB2;
    uint32_t bh0[5][2], bl0[5][2], bh1[5][2], bl1[5][2];
    uint32_t ah[2][4], al[2][4];
    loadB(Bh, Bl, 0, bh0, bl0, g, t, n0w);
    loadA32(s_Ah2, s_Al2, kp0, ah, al, g, t, m0w);
    loadB(Bh, Bl, 1, bh1, bl1, g, t, n0w);
    MMA_T5x2(acc, ah, bh0);
    MMA_T5x2(acc, al, bh0);
    MMA_T5x2(acc, ah, bl0);
    loadA32(s_Ah2, s_Al2, kp0 + 8, ah, al, g, t, m0w);
    MMA_T5x2(acc, ah, bh1);
    MMA_T5x2(acc, al, bh1);
    MMA_T5x2(acc, ah, bl1);
}

__device__ __forceinline__ void gemm32(const uint32_t* __restrict__ gW,
                                       const uint32_t* __restrict__ gWnext,
                                       uint32_t* sB0, uint32_t* sB1,
                                       float acc[5][2][4],
                                       const uint32_t* s_Ah2, const uint32_t* s_Al2,
                                       int par0, int tid, int g, int t, int m0w, int n0w) {
#pragma unroll 1
    for (int c = 0; c < 5; ++c) {
        uint32_t* cur = ((par0 + c) & 1) ? sB1 : sB0;
        uint32_t* nxt = ((par0 + c) & 1) ? sB0 : sB1;
        if (c < 4) {
            stage_chunk256(nxt, gW + (size_t)(c + 1) * CHUNK_U32, tid);
            CP_COMMIT(); CP_WAIT1();
        } else if (gWnext) {
            stage_chunk256(nxt, gWnext, tid);
            CP_COMMIT(); CP_WAIT1();
        } else {
            CP_WAIT0();
        }
        __syncthreads();
        mma_chunk32(cur, acc, s_Ah2, s_Al2, c * 16, g, t, m0w, n0w);
        __syncthreads();
    }
}

// 16-row x 40-col chunk (stage B GEMM2, 512 threads)
__device__ __forceinline__ void mma_chunk16(const uint32_t* sB, float acc[5][4],
                                            const uint32_t* Ah, const uint32_t* Al,
                                            int kp0, int g, int t, int m0w, int n0w) {
    const uint32_t* Bh = sB;
    const uint32_t* Bl = sB + 16 * PB2;
    uint32_t bh0[5][2], bl0[5][2], bh1[5][2], bl1[5][2];
    uint32_t ah[4], al[4];
    loadB(Bh, Bl, 0, bh0, bl0, g, t, n0w);
    loadA16(Ah, Al, PA2, kp0, ah, al, g, t, m0w);
    loadB(Bh, Bl, 1, bh1, bl1, g, t, n0w);
    MMA_T5(acc, ah, bh0);
    MMA_T5(acc, al, bh0);
    MMA_T5(acc, ah, bl0);
    loadA16(Ah, Al, PA2, kp0 + 8, ah, al, g, t, m0w);
    MMA_T5(acc, ah, bh1);
    MMA_T5(acc, al, bh1);
    MMA_T5(acc, ah, bl1);
}

__device__ __forceinline__ void gemm16(const uint32_t* __restrict__ gW,
                                       uint32_t* sB0, uint32_t* sB1,
                                       float acc[5][4],
                                       const uint32_t* Ah, const uint32_t* Al,
                                       int tid, int g, int t, int m0w, int n0w) {
#pragma unroll 1
    for (int c = 0; c < 5; ++c) {
        uint32_t* cur = (c & 1) ? sB1 : sB0;
        uint32_t* nxt = (c & 1) ? sB0 : sB1;
        if (c < 4) {
            stage_chunk512(nxt, gW + (size_t)(c + 1) * CHUNK_U32, tid);
            CP_COMMIT(); CP_WAIT1();
        } else {
            CP_WAIT0();
        }
        __syncthreads();
        mma_chunk16(cur, acc, Ah, Al, c * 16, g, t, m0w, n0w);
        __syncthreads();
    }
}

#define ZERO_A524(acc) \
    _Pragma("unroll") for (int f = 0; f < 5; ++f) \
    _Pragma("unroll") for (int mf = 0; mf < 2; ++mf) \
    _Pragma("unroll") for (int r = 0; r < 4; ++r) acc[f][mf][r] = 0.f;
#define ZERO_A54(acc) \
    _Pragma("unroll") for (int f = 0; f < 5; ++f) \
    _Pragma("unroll") for (int r = 0; r < 4; ++r) acc[f][r] = 0.f;
#define ZERO_A64(acc) \
    _Pragma("unroll") for (int f = 0; f < 6; ++f) \
    _Pragma("unroll") for (int r = 0; r < 4; ++r) acc[f][r] = 0.f;

// ===================== stage A: 256 threads, 64-token tile, 2 CTAs/SM =====================
__global__ void __launch_bounds__(256, 2) stageA_mma(
    const float* __restrict__ b1, const float* __restrict__ b2,
    const float* __restrict__ bg, const float* __restrict__ bv,
    const float* __restrict__ lns, const float* __restrict__ lnb)
{
    float* s_bias = smem;                        // 6*160
    float* s_red  = s_bias + 6 * HD;             // 128
    uint32_t* s_Ah2 = (uint32_t*)(s_red + 128);  // [64][84]
    uint32_t* s_Al2 = s_Ah2 + TA * PA2;
    uint32_t* sB0   = s_Al2 + TA * PA2;
    uint32_t* sB1   = sB0 + CHUNK_U32;

    const int v   = blockIdx.x;
    const int n0  = blockIdx.y * TA;
    const int tid = threadIdx.x;
    const int lane = tid & 31;
    const int wid  = tid >> 5;                   // 0..7
    const int g = lane >> 2, t = lane & 3;
    const int m0w = (wid & 1) * 32;
    const int n0w = (wid >> 1) * 40;
    const int pib = n0w / 2;

    const uint32_t* wbase = g_wsplA + (size_t)v * 20 * CHUNK_U32;

    stage_chunk256(sB0, wbase, tid);
    CP_COMMIT();

    for (int l = tid; l < HD; l += 256) {
        s_bias[l]          = b1[v * HD + l];
        s_bias[HD + l]     = b2[v * HD + l];
        s_bias[2*HD + l]   = bg[v * HD + l];
        s_bias[3*HD + l]   = bv[v * HD + l];
        s_bias[4*HD + l]   = lns[v * HD + l];
        s_bias[5*HD + l]   = lnb[v * HD + l];
    }

    // x tile: coalesced from g_embt; split-pack into A buffers
#pragma unroll
    for (int u = 0; u < 20; ++u) {
        int p = u * 256 + tid;                   // 64*80 pairs
        int row = p / 80, pc = p - row * 80;
        float2 xv = *(const float2*)(g_embt + (size_t)(n0 + row) * (HD * NV) + (size_t)v * HD + 2 * pc);
        uint32_t hi, lo;
        splitpack(xv.x, xv.y, hi, lo);
        s_Ah2[row * PA2 + pc] = hi;
        s_Al2[row * PA2 + pc] = lo;
    }
    __syncthreads();

    float acc[5][2][4];

    // GEMM1: h1 = elu(x@W1 + b1)
    ZERO_A524(acc);
    gemm32(wbase, wbase + 5 * CHUNK_U32, sB0, sB1, acc, s_Ah2, s_Al2, 0, tid, g, t, m0w, n0w);
#pragma unroll
    for (int f = 0; f < 5; ++f) {
        int col0 = n0w + f * 8 + 2 * t;
        int pi = pib + f * 4 + t;
#pragma unroll
        for (int mf = 0; mf < 2; ++mf) {
            int r0 = m0w + mf * 16 + g;
            float v00 = eluf(acc[f][mf][0] + s_bias[col0]);
            float v01 = eluf(acc[f][mf][1] + s_bias[col0 + 1]);
            float v10 = eluf(acc[f][mf][2] + s_bias[col0]);
            float v11 = eluf(acc[f][mf][3] + s_bias[col0 + 1]);
            splitpack(v00, v01, s_Ah2[r0 * PA2 + pi], s_Al2[r0 * PA2 + pi]);
            splitpack(v10, v11, s_Ah2[(r0 + 8) * PA2 + pi], s_Al2[(r0 + 8) * PA2 + pi]);
        }
    }

    // GEMM2: h2 = h1@W2 + b2
    ZERO_A524(acc);
    gemm32(wbase + 5 * CHUNK_U32, wbase + 10 * CHUNK_U32, sB0, sB1, acc, s_Ah2, s_Al2, 1, tid, g, t, m0w, n0w);
#pragma unroll
    for (int f = 0; f < 5; ++f) {
        int col0 = n0w + f * 8 + 2 * t;
        int pi = pib + f * 4 + t;
#pragma unroll
        for (int mf = 0; mf < 2; ++mf) {
            int r0 = m0w + mf * 16 + g;
            float v00 = acc[f][mf][0] + s_bias[HD + col0];
            float v01 = acc[f][mf][1] + s_bias[HD + col0 + 1];
            float v10 = acc[f][mf][2] + s_bias[HD + col0];
            float v11 = acc[f][mf][3] + s_bias[HD + col0 + 1];
            splitpack(v00, v01, s_Ah2[r0 * PA2 + pi], s_Al2[r0 * PA2 + pi]);
            splitpack(v10, v11, s_Ah2[(r0 + 8) * PA2 + pi], s_Al2[(r0 + 8) * PA2 + pi]);
        }
    }

    // GEMM3: gate = sigmoid(h2@Wg + bg)
    ZERO_A524(acc);
    gemm32(wbase + 10 * CHUNK_U32, wbase + 15 * CHUNK_U32, sB0, sB1, acc, s_Ah2, s_Al2, 0, tid, g, t, m0w, n0w);
    float gate[5][2][4];
#pragma unroll
    for (int f = 0; f < 5; ++f)
#pragma unroll
        for (int mf = 0; mf < 2; ++mf)
#pragma unroll
            for (int r = 0; r < 4; ++r) {
                int col = n0w + f * 8 + 2 * t + (r & 1);
                gate[f][mf][r] = sigf(acc[f][mf][r] + s_bias[2*HD + col]);
            }

    // GEMM4: y = x + gate*(h2@Wv + bv)  (x re-read from g_embt; y -> packed A)
    ZERO_A524(acc);
    gemm32(wbase + 15 * CHUNK_U32, (const uint32_t*)0, sB0, sB1, acc, s_Ah2, s_Al2, 1, tid, g, t, m0w, n0w);
#pragma unroll
    for (int f = 0; f < 5; ++f) {
        int col0 = n0w + f * 8 + 2 * t;
        int pi = pib + f * 4 + t;
#pragma unroll
        for (int mf = 0; mf < 2; ++mf) {
            int r0 = m0w + mf * 16 + g;
            float2 x0 = *(const float2*)(g_embt + (size_t)(n0 + r0) * (HD * NV) + (size_t)v * HD + col0);
            float2 x1 = *(const float2*)(g_embt + (size_t)(n0 + r0 + 8) * (HD * NV) + (size_t)v * HD + col0);
            float y00 = x0.x + gate[f][mf][0] * (acc[f][mf][0] + s_bias[3*HD + col0]);
            float y01 = x0.y + gate[f][mf][1] * (acc[f][mf][1] + s_bias[3*HD + col0 + 1]);
            float y10 = x1.x + gate[f][mf][2] * (acc[f][mf][2] + s_bias[3*HD + col0]);
            float y11 = x1.y + gate[f][mf][3] * (acc[f][mf][3] + s_bias[3*HD + col0 + 1]);
            splitpack(y00, y01, s_Ah2[r0 * PA2 + pi], s_Al2[r0 * PA2 + pi]);
            splitpack(y10, y11, s_Ah2[(r0 + 8) * PA2 + pi], s_Al2[(r0 + 8) * PA2 + pi]);
        }
    }
    __syncthreads();

    // LayerNorm stats: warp w owns rows 8w..8w+7
#pragma unroll
    for (int rr = 0; rr < 8; ++rr) {
        int row = 8 * wid + rr;
        float s = 0.f, q = 0.f;
#pragma unroll
        for (int u = 0; u < 3; ++u) {
            int pc = u * 32 + lane;
            if (pc < 80) {
                float2 y = unpk(s_Ah2[row * PA2 + pc], s_Al2[row * PA2 + pc]);
                s += y.x + y.y;
                q += y.x * y.x + y.y * y.y;
            }
        }
#pragma unroll
        for (int off = 16; off; off >>= 1) {
            s += __shfl_xor_sync(0xffffffffu, s, off);
            q += __shfl_xor_sync(0xffffffffu, q, off);
        }
        if (lane == 0) {
            float mean = s * (1.f / HD);
            float var  = q * (1.f / HD) - mean * mean;
            s_red[row * 2]     = mean;
            s_red[row * 2 + 1] = rsqrtf(var + 1e-5f);
        }
    }
    __syncthreads();

    // normalized y -> g_trh/g_trl (coalesced)
#pragma unroll
    for (int u = 0; u < 20; ++u) {
        int p = u * 256 + tid;
        int row = p / 80, pc = p - row * 80;
        float mean = s_red[row * 2], rstd = s_red[row * 2 + 1];
        int j0 = 2 * pc, j1 = 2 * pc + 1;
        float2 y = unpk(s_Ah2[row * PA2 + pc], s_Al2[row * PA2 + pc]);
        float y0 = (y.x - mean) * rstd * s_bias[4*HD + j0] + s_bias[5*HD + j0];
        float y1 = (y.y - mean) * rstd * s_bias[4*HD + j1] + s_bias[5*HD + j1];
        uint32_t hi, lo;
        splitpack(y0, y1, hi, lo);
        size_t base = (size_t)(n0 + row) * (NV * 80) + (size_t)v * 80 + pc;
        g_trh[base] = hi;
        g_trl[base] = lo;
    }
}

// ===================== transpose / ctx =====================
__global__ void __launch_bounds__(256) transpose_kernel(const float* __restrict__ emb) {
    __shared__ float s[HD * 17];
    size_t n = blockIdx.x;
    int tid = threadIdx.x;
    const float* src = emb + n * (HD * NV);
    for (int l = tid; l < HD * NV; l += 256) {
        int e = l >> 4, vv = l & 15;
        s[e * 17 + vv] = src[l];
    }
    __syncthreads();
    float* dst = g_embt + n * (HD * NV);
    for (int l = tid; l < HD * NV; l += 256) {
        int vv = l / HD, e = l - vv * HD;
        dst[l] = s[e * 17 + vv];
    }
}

__global__ void ctx_kernel(const float* __restrict__ ac, const float* __restrict__ Wc) {
    int b = blockIdx.x, j = threadIdx.x;
    float s = 0.f;
    for (int k = 0; k < HD; ++k)
        s = fmaf(ac[b * HD + k], Wc[k * HD + j], s);
    g_ctx[b * HD + j] = s;
}

// ===================== stage B: 512 threads, 64-token tile (R8-proven) =====================
__device__ __forceinline__ void stageB_chunk(uint32_t* dAh, uint32_t* dAl, uint32_t* dB,
                                             int n0, int c, int tid) {
    if (tid < 256) {
        int r = tid >> 2, q = tid & 3;
        size_t abase = (size_t)(n0 + r) * (NV * 80) + (size_t)c * 16 + q * 4;
        cp16(smem_u32(dAh + r * PAB + q * 4), g_trh + abase);
    } else {
        int t2 = tid - 256;
        int r = t2 >> 2, q = t2 & 3;
        size_t abase = (size_t)(n0 + r) * (NV * 80) + (size_t)c * 16 + q * 4;
        cp16(smem_u32(dAl + r * PAB + q * 4), g_trl + abase);
    }
    const uint32_t* gsrc = g_wsplB1 + (size_t)c * CHUNKB;
    uint32_t db = smem_u32(dB);
#pragma unroll
    for (int i = 0; i < 4; ++i) {
        int idx = i * 512 + tid;
        if (idx < 1600) cp16(db + idx * 16, gsrc + idx * 4);
    }
}

__device__ __forceinline__ void mma_chunkB(const uint32_t* A_h, const uint32_t* A_l,
                                           const uint32_t* B, float acc[6][4],
                                           int g, int t, int m0w, int n0w48) {
    const uint32_t* Bh = B;
    const uint32_t* Bl = B + 16 * PBB;
#pragma unroll
    for (int s = 0; s < 2; ++s) {
        int kp = s * 8;
        uint32_t ah[4], al[4], bh[6][2], bl[6][2];
        loadA16(A_h, A_l, PAB, kp, ah, al, g, t, m0w);
#pragma unroll
        for (int f = 0; f < 6; ++f) {
            int nn = n0w48 + f * 8 + g;
            bh[f][0] = Bh[(kp + t) * PBB + nn]; bh[f][1] = Bh[(kp + 4 + t) * PBB + nn];
            bl[f][0] = Bl[(kp + t) * PBB + nn]; bl[f][1] = Bl[(kp + 4 + t) * PBB + nn];
        }
        MMA_T6(acc, ah, bh);
        MMA_T6(acc, al, bh);
        MMA_T6(acc, ah, bl);
    }
}

__global__ void __launch_bounds__(512, 1) stageB_mma(
    const float* __restrict__ b1,  const float* __restrict__ b2,
    const float* __restrict__ bsk, const float* __restrict__ bg,
    const float* __restrict__ bv,  const float* __restrict__ lns,
    const float* __restrict__ lnb, const float* __restrict__ Wg,
    const float* __restrict__ Wv,
    float* __restrict__ out_sw, float* __restrict__ out_sg)
{
    uint32_t* sm   = (uint32_t*)smem;
    uint32_t* bufr = sm;                       // 17920 u32 union region
    uint32_t* s_Ah2 = sm + 17920;              // [64][84]
    uint32_t* s_Al2 = s_Ah2 + TA * PA2;
    float* s_h3 = (float*)(s_Al2 + TA * PA2);  // [160][65]
    float* s_sk = s_h3 + 160 * 65;             // [64][16]
    float* s_gv = s_sk + TA * NV;              // [160][32]
    float* s_cb = s_gv + HD * 32;              // 400

    uint32_t* sAh[2] = { bufr,        bufr + 2560 };
    uint32_t* sAl[2] = { bufr + 1280, bufr + 3840 };
    uint32_t* sBB[2] = { bufr + 5120, bufr + 5120 + CHUNKB };
    uint32_t* sB20 = bufr;
    uint32_t* sB21 = bufr + CHUNK_U32;

    const int n0  = blockIdx.x * TA;
    const int tid = threadIdx.x;
    const int lane = tid & 31;
    const int wid  = tid >> 5;                 // 0..15
    const int g = lane >> 2, t = lane & 3;
    const int m0w16 = (wid & 3) * 16;
    const int n0w48 = (wid >> 2) * 48;
    const int n0w40 = (wid >> 2) * 40;
    const int bidx  = n0 >> 9;

    stageB_chunk(sAh[0], sAl[0], sBB[0], n0, 0, tid);
    CP_COMMIT();

    if (tid < HD) {
        s_cb[tid]       = b1[tid] + g_ctx[bidx * HD + tid];
        s_cb[HD + tid]  = b2[tid];
    }
    if (tid < NV) {
        s_cb[320 + tid] = bg[tid];
        s_cb[336 + tid] = bv[tid];
        s_cb[352 + tid] = lns[tid];
        s_cb[368 + tid] = lnb[tid];
        s_cb[384 + tid] = bsk[tid];
    }
#pragma unroll
    for (int u = 0; u < 10; ++u) {
        int l = u * 512 + tid;
        int cc = l & 31, k = l >> 5;
        s_gv[k * 32 + cc] = (cc < NV) ? Wg[k * NV + cc] : Wv[k * NV + (cc - NV)];
    }

    float acc[6][4];
    ZERO_A64(acc);

#pragma unroll 1
    for (int c = 0; c < 80; ++c) {
        int cur = c & 1, nxt = cur ^ 1;
        if (c < 79) {
            stageB_chunk(sAh[nxt], sAl[nxt], sBB[nxt], n0, c + 1, tid);
            CP_COMMIT(); CP_WAIT1();
        } else {
            CP_WAIT0();
        }
        __syncthreads();
        mma_chunkB(sAh[cur], sAl[cur], sBB[cur], acc, g, t, m0w16, n0w48);
        __syncthreads();
    }

#pragma unroll
    for (int f = 0; f < 6; ++f) {
        int col0 = n0w48 + f * 8 + 2 * t;
        int r0 = m0w16 + g;
        float v00 = acc[f][0], v01 = acc[f][1];
        float v10 = acc[f][2], v11 = acc[f][3];
        if (col0 < HD) {
            int pi = col0 >> 1;
            float e00 = eluf(v00 + s_cb[col0]);
            float e01 = eluf(v01 + s_cb[col0 + 1]);
            float e10 = eluf(v10 + s_cb[col0]);
            float e11 = eluf(v11 + s_cb[col0 + 1]);
            splitpack(e00, e01, s_Ah2[r0 * PA2 + pi], s_Al2[r0 * PA2 + pi]);
            splitpack(e10, e11, s_Ah2[(r0 + 8) * PA2 + pi], s_Al2[(r0 + 8) * PA2 + pi]);
        } else if (col0 < HD + NV) {
            int sc = col0 - HD;
            s_sk[r0 * NV + sc]           = v00;
            s_sk[r0 * NV + sc + 1]       = v01;
            s_sk[(r0 + 8) * NV + sc]     = v10;
            s_sk[(r0 + 8) * NV + sc + 1] = v11;
        }
    }
    __syncthreads();

    stage_chunk512(sB20, g_wsplB2, tid);
    CP_COMMIT();

    float acc5[5][4];
    ZERO_A54(acc5);
    gemm16(g_wsplB2, sB20, sB21, acc5, s_Ah2, s_Al2, tid, g, t, m0w16, n0w40);
#pragma unroll
    for (int f = 0; f < 5; ++f)
#pragma unroll
        for (int r = 0; r < 4; ++r) {
            int row = m0w16 + g + (r >> 1) * 8;
            int col = n0w40 + f * 8 + 2 * t + (r & 1);
            s_h3[col * 65 + row] = acc5[f][r] + s_cb[HD + col];
        }
    __syncthreads();

    float gv[4] = {0.f, 0.f, 0.f, 0.f};
    const int c = lane;
#pragma unroll 4
    for (int k = 0; k < HD; ++k) {
        float w = s_gv[k * 32 + c];
        const float* h3k = s_h3 + k * 65 + 4 * wid;
#pragma unroll
        for (int rr = 0; rr < 4; ++rr)
            gv[rr] = fmaf(h3k[rr], w, gv[rr]);
    }

    int vc = c & 15;
    float bgv = (c < NV) ? s_cb[320 + vc] : s_cb[336 + vc];
    float skb = s_cb[384 + vc];
    float lsc = s_cb[352 + vc], lbc = s_cb[368 + vc];
#pragma unroll
    for (int rr = 0; rr < 4; ++rr) {
        int row = 4 * wid + rr;
        float z = gv[rr] + bgv;
        float gval = (c < NV) ? sigf(z) : z;
        float partner = __shfl_xor_sync(0xffffffffu, gval, 16);
        float y = s_sk[row * NV + vc] + skb + gval * partner;
        float s = y, q = y * y;
#pragma unroll
        for (int off = 8; off; off >>= 1) {
            s += __shfl_xor_sync(0xffffffffu, s, off);
            q += __shfl_xor_sync(0xffffffffu, q, off);
        }
        float mean = s * (1.f / 16.f);
        float var  = q * (1.f / 16.f) - mean * mean;
        float rstd = rsqrtf(var + 1e-5f);
        float logit = (y - mean) * rstd * lsc + lbc;
        float mx = logit;
#pragma unroll
        for (int off = 8; off; off >>= 1)
            mx = fmaxf(mx, __shfl_xor_sync(0xffffffffu, mx, off));
        float e = expf(logit - mx);
        float se = e;
#pragma unroll
        for (int off = 8; off; off >>= 1)
            se += __shfl_xor_sync(0xffffffffu, se, off);
        if (c < NV) {
            int n = n0 + row;
            out_sw[(size_t)n * NV + c] = e / se;
            out_sg[(size_t)n * NV + c] = gval;
        }
    }
}

// ===================== stage C =====================
__global__ void __launch_bounds__(256) stageC_kernel(const float* __restrict__ sw,
                                                     float* __restrict__ out_tc) {
    __shared__ float s_w[16 * NV];
    int n0 = blockIdx.x * 16;
    int tid = threadIdx.x;
    s_w[tid] = sw[(size_t)n0 * NV + tid];
    __syncthreads();
#pragma unroll
    for (int u = 0; u < 5; ++u) {
        int l = u * 256 + tid;
        int m = l / 80, pc = l - m * 80;
        size_t base = (size_t)(n0 + m) * (NV * 80) + pc;
        float a0 = 0.f, a1 = 0.f;
#pragma unroll
        for (int vv = 0; vv < NV; ++vv) {
            float2 x = unpk(g_trh[base + vv * 80], g_trl[base + vv * 80]);
            float w = s_w[m * NV + vv];
            a0 = fmaf(x.x, w, a0);
            a1 = fmaf(x.y, w, a1);
        }
        float* dst = out_tc + (size_t)(n0 + m) * HD + 2 * pc;
        dst[0] = a0;
        dst[1] = a1;
    }
}

// ===================== launch =====================
extern "C" void kernel_launch(void* const* d_in, const int* in_sizes, int n_in,
                              void* d_out, int out_size)
{
    const float* emb   = (const float*)d_in[0];
    const float* ac    = (const float*)d_in[1];
    const float* sv_W1 = (const float*)d_in[2];
    const float* sv_b1 = (const float*)d_in[3];
    const float* sv_W2 = (const float*)d_in[4];
    const float* sv_b2 = (const float*)d_in[5];
    const float* sv_Wg = (const float*)d_in[6];
    const float* sv_bg = (const float*)d_in[7];
    const float* sv_Wv = (const float*)d_in[8];
    const float* sv_bv = (const float*)d_in[9];
    const float* sv_ls = (const float*)d_in[10];
    const float* sv_lb = (const float*)d_in[11];
    const float* fWsk  = (const float*)d_in[12];
    const float* fbsk  = (const float*)d_in[13];
    const float* fW1   = (const float*)d_in[14];
    const float* fb1   = (const float*)d_in[15];
    const float* fWc   = (const float*)d_in[16];
    const float* fW2   = (const float*)d_in[17];
    const float* fb2   = (const float*)d_in[18];
    const float* fWg   = (const float*)d_in[19];
    const float* fbg   = (const float*)d_in[20];
    const float* fWv   = (const float*)d_in[21];
    const float* fbv   = (const float*)d_in[22];
    const float* fls   = (const float*)d_in[23];
    const float* flb   = (const float*)d_in[24];

    float* out    = (float*)d_out;
    float* out_tc = out;
    float* out_sw = out + (size_t)NTOK * HD;
    float* out_sg = out_sw + (size_t)NTOK * NV;

    const int SMEM_A = (6 * HD + 128) * 4 + (2 * TA * PA2 + 2 * CHUNK_U32) * 4;   // 90,368 (2 CTAs/SM)
    const int SMEM_B = (17920 + 2 * TA * PA2) * 4 + (160 * 65 + TA * NV + HD * 32 + 400) * 4;
    cudaFuncSetAttribute(stageA_mma, cudaFuncAttributeMaxDynamicSharedMemorySize, SMEM_A);
    cudaFuncSetAttribute(stageB_mma, cudaFuncAttributeMaxDynamicSharedMemorySize, SMEM_B);

    prepA_kernel<<<320, 256>>>(sv_W1, sv_W2, sv_Wg, sv_Wv);
    prepB1_kernel<<<80, 256>>>(fW1, fWsk);
    prepB2_kernel<<<5, 256>>>(fW2);
    ctx_kernel<<<64, HD>>>(ac, fWc);
    transpose_kernel<<<NTOK, 256>>>(emb);
    stageA_mma<<<dim3(NV, NTOK / TA), 256, SMEM_A>>>(sv_b1, sv_b2, sv_bg, sv_bv, sv_ls, sv_lb);
    stageB_mma<<<NTOK / TA, 512, SMEM_B>>>(fb1, fb2, fbsk, fbg, fbv, fls, flb,
                                           fWg, fWv, out_sw, out_sg);
    stageC_kernel<<<NTOK / 16, 256>>>(out_sw, out_tc);
}

// round 14
// speedup vs baseline: 1.0021x; 1.0021x over previous
#include <cuda_runtime.h>
#include <cuda_bf16.h>
#include <math.h>
#include <stdint.h>

#define NTOK 32768        // B*T
#define HD   160          // hidden = embed
#define NV   16           // variables
#define TA   64           // stage A + B token tile
#define PA2  84           // packed-A pitch (u32)  -> conflict-free
#define PB2  168          // packed-B pitch (u32)  -> conflict-free
#define CHUNK_U32 (2*16*PB2)   // 5376 u32: hi tile [16][168] then lo tile
#define PAB  20           // stage B big-A pitch (u32)
#define PBB  200          // stage B big-B pitch (u32)
#define CHUNKB 6400       // u32 per big-B chunk (hi 3200 + lo 3200)

static __device__ float g_embt[(size_t)NTOK * HD * NV];  // emb transposed [n][v][e]
static __device__ float g_ctx[64 * HD];
static __device__ __align__(16) uint32_t g_trh[(size_t)NTOK * NV * 80];
static __device__ __align__(16) uint32_t g_trl[(size_t)NTOK * NV * 80];
static __device__ __align__(16) uint32_t g_wsplA[(size_t)16 * 4 * 5 * CHUNK_U32];
static __device__ __align__(16) uint32_t g_wsplB1[(size_t)80 * CHUNKB];
static __device__ __align__(16) uint32_t g_wsplB2[(size_t)5 * CHUNK_U32];

__device__ __forceinline__ float eluf(float x) { return x > 0.f ? x : expm1f(x); }
__device__ __forceinline__ float sigf(float x) { return 1.f / (1.f + expf(-x)); }

__device__ __forceinline__ uint32_t smem_u32(const void* p) {
    uint32_t a;
    asm("{ .reg .u64 t; cvta.to.shared.u64 t, %1; cvt.u32.u64 %0, t; }" : "=r"(a) : "l"(p));
    return a;
}
__device__ __forceinline__ void cp16(uint32_t saddr, const uint32_t* g) {
    asm volatile("cp.async.cg.shared.global [%0], [%1], 16;" :: "r"(saddr), "l"(g));
}
#define CP_COMMIT() asm volatile("cp.async.commit_group;" ::: "memory")
#define CP_WAIT1()  asm volatile("cp.async.wait_group 1;" ::: "memory")
#define CP_WAIT0()  asm volatile("cp.async.wait_group 0;" ::: "memory")

__device__ __forceinline__ void mma16(float* c, const uint32_t* a, const uint32_t* b) {
    asm volatile("mma.sync.aligned.m16n8k16.row.col.f32.bf16.bf16.f32 "
        "{%0,%1,%2,%3}, {%4,%5,%6,%7}, {%8,%9}, {%0,%1,%2,%3};"
        : "+f"(c[0]), "+f"(c[1]), "+f"(c[2]), "+f"(c[3])
        : "r"(a[0]), "r"(a[1]), "r"(a[2]), "r"(a[3]), "r"(b[0]), "r"(b[1]));
}

__device__ __forceinline__ void splitpack(float v0, float v1, uint32_t& hi, uint32_t& lo) {
    __nv_bfloat16 h0 = __float2bfloat16(v0), h1 = __float2bfloat16(v1);
    __nv_bfloat16 l0 = __float2bfloat16(v0 - __bfloat162float(h0));
    __nv_bfloat16 l1 = __float2bfloat16(v1 - __bfloat162float(h1));
    __nv_bfloat162 hh; hh.x = h0; hh.y = h1;
    __nv_bfloat162 ll; ll.x = l0; ll.y = l1;
    hi = *reinterpret_cast<uint32_t*>(&hh);
    lo = *reinterpret_cast<uint32_t*>(&ll);
}
__device__ __forceinline__ float2 unpk(uint32_t hi, uint32_t lo) {
    __nv_bfloat162 h = *reinterpret_cast<__nv_bfloat162*>(&hi);
    __nv_bfloat162 l = *reinterpret_cast<__nv_bfloat162*>(&lo);
    float2 r;
    r.x = __bfloat162float(h.x) + __bfloat162float(l.x);
    r.y = __bfloat162float(h.y) + __bfloat162float(l.y);
    return r;
}

// ===================== prep kernels (unchanged) =====================
__global__ void __launch_bounds__(256) prepA_kernel(
    const float* __restrict__ W1, const float* __restrict__ W2,
    const float* __restrict__ Wg, const float* __restrict__ Wv)
{
    int b = blockIdx.x;
    int c = b % 5, mat = (b / 5) & 3, v = b / 20;
    const float* W = (mat == 0 ? W1 : mat == 1 ? W2 : mat == 2 ? Wg : Wv) + (size_t)v * HD * HD;
    uint32_t* dst = g_wsplA + (size_t)b * CHUNK_U32;
    for (int i = threadIdx.x; i < 16 * PB2; i += 256) {
        int pr = i / PB2, col = i - pr * PB2;
        float w0 = 0.f, w1 = 0.f;
        if (col < HD) {
            int k0 = c * 32 + 2 * pr;
            w0 = W[(size_t)k0 * HD + col];
            w1 = W[(size_t)(k0 + 1) * HD + col];
        }
        uint32_t hi, lo;
        splitpack(w0, w1, hi, lo);
        dst[i] = hi;
        dst[16 * PB2 + i] = lo;
    }
}

__global__ void __launch_bounds__(256) prepB1_kernel(
    const float* __restrict__ W1, const float* __restrict__ Wsk)
{
    int c = blockIdx.x;
    uint32_t* dst = g_wsplB1 + (size_t)c * CHUNKB;
    for (int i = threadIdx.x; i < 16 * PBB; i += 256) {
        int pr = i / PBB, col = i - pr * PBB;
        int k0 = c * 32 + 2 * pr, k1 = k0 + 1;
        int pk0 = (k0 % HD) * NV + (k0 / HD);
        int pk1 = (k1 % HD) * NV + (k1 / HD);
        float w0 = 0.f, w1 = 0.f;
        if (col < HD) {
            w0 = W1[(size_t)pk0 * HD + col];
            w1 = W1[(size_t)pk1 * HD + col];
        } else if (col < HD + NV) {
            w0 = Wsk[(size_t)pk0 * NV + (col - HD)];
            w1 = Wsk[(size_t)pk1 * NV + (col - HD)];
        }
        uint32_t hi, lo;
        splitpack(w0, w1, hi, lo);
        dst[i] = hi;
        dst[16 * PBB + i] = lo;
    }
}

__global__ void __launch_bounds__(256) prepB2_kernel(const float* __restrict__ W2) {
    int c = blockIdx.x;
    uint32_t* dst = g_wsplB2 + (size_t)c * CHUNK_U32;
    for (int i = threadIdx.x; i < 16 * PB2; i += 256) {
        int pr = i / PB2, col = i - pr * PB2;
        float w0 = 0.f, w1 = 0.f;
        if (col < HD) {
            int k0 = c * 32 + 2 * pr;
            w0 = W2[(size_t)k0 * HD + col];
            w1 = W2[(size_t)(k0 + 1) * HD + col];
        }
        uint32_t hi, lo;
        splitpack(w0, w1, hi, lo);
        dst[i] = hi;
        dst[16 * PB2 + i] = lo;
    }
}

// ===================== shared mma machinery =====================
extern __shared__ float smem[];

// stage one CHUNK_U32 (1344 cp16) with 256 threads
__device__ __forceinline__ void stage_chunk256(uint32_t* sdst, const uint32_t* __restrict__ g, int tid) {
    uint32_t s = smem_u32(sdst);
#pragma unroll
    for (int i = 0; i < 5; ++i) {
        int q = i * 256 + tid;
        cp16(s + q * 16, g + q * 4);
    }
    int q = 1280 + tid;
    if (q < 1344) cp16(s + q * 16, g + q * 4);
}
// same with 512 threads
__device__ __forceinline__ void stage_chunk512(uint32_t* sdst, const uint32_t* __restrict__ g, int tid) {
    uint32_t s = smem_u32(sdst);
#pragma unroll
    for (int i = 0; i < 2; ++i) {
        int q = i * 512 + tid;
        cp16(s + q * 16, g + q * 4);
    }
    int q = 1024 + tid;
    if (q < 1344) cp16(s + q * 16, g + q * 4);
}

__device__ __forceinline__ void loadB(const uint32_t* Bh, const uint32_t* Bl, int s,
                                      uint32_t bh[5][2], uint32_t bl[5][2],
                                      int g, int t, int n0w) {
#pragma unroll
    for (int f = 0; f < 5; ++f) {
        int nn = n0w + f * 8 + g;
        bh[f][0] = Bh[(s * 8 + t) * PB2 + nn];
        bh[f][1] = Bh[(s * 8 + 4 + t) * PB2 + nn];
        bl[f][0] = Bl[(s * 8 + t) * PB2 + nn];
        bl[f][1] = Bl[(s * 8 + 4 + t) * PB2 + nn];
    }
}

__device__ __forceinline__ void loadA32(const uint32_t* s_Ah2, const uint32_t* s_Al2, int kp,
                                        uint32_t ah[2][4], uint32_t al[2][4],
                                        int g, int t, int m0w) {
#pragma unroll
    for (int mf = 0; mf < 2; ++mf) {
        int r0 = (m0w + mf * 16 + g) * PA2;
        int r1 = r0 + 8 * PA2;
        ah[mf][0] = s_Ah2[r0 + kp + t];     ah[mf][1] = s_Ah2[r1 + kp + t];
        ah[mf][2] = s_Ah2[r0 + kp + 4 + t]; ah[mf][3] = s_Ah2[r1 + kp + 4 + t];
        al[mf][0] = s_Al2[r0 + kp + t];     al[mf][1] = s_Al2[r1 + kp + t];
        al[mf][2] = s_Al2[r0 + kp + 4 + t]; al[mf][3] = s_Al2[r1 + kp + 4 + t];
    }
}

__device__ __forceinline__ void loadA16(const uint32_t* Ah, const uint32_t* Al, int pitch, int kp,
                                        uint32_t ah[4], uint32_t al[4], int g, int t, int m0w) {
    int r0 = (m0w + g) * pitch;
    int r1 = r0 + 8 * pitch;
    ah[0] = Ah[r0 + kp + t];     ah[1] = Ah[r1 + kp + t];
    ah[2] = Ah[r0 + kp + 4 + t]; ah[3] = Ah[r1 + kp + 4 + t];
    al[0] = Al[r0 + kp + t];     al[1] = Al[r1 + kp + t];
    al[2] = Al[r0 + kp + 4 + t]; al[3] = Al[r1 + kp + 4 + t];
}

#define MMA_T5x2(acc, A, B) \
    _Pragma("unroll") for (int f_ = 0; f_ < 5; ++f_) \
    _Pragma("unroll") for (int mf_ = 0; mf_ < 2; ++mf_) \
        mma16(acc[f_][mf_], (A)[mf_], (B)[f_]);
#define MMA_T5(acc, A, B) \
    _Pragma("unroll") for (int f_ = 0; f_ < 5; ++f_) \
        mma16(acc[f_], (A), (B)[f_]);
#define MMA_T6(acc, A, B) \
    _Pragma("unroll") for (int f_ = 0; f_ < 6; ++f_) \
        mma16(acc[f_], (A), (B)[f_]);

// 32-row x 40-col chunk (stage A)
__device__ __forceinline__ void mma_chunk32(const uint32_t* sB, float acc[5][2][4],
                                            const uint32_t* s_Ah2, const uint32_t* s_Al2,
                                            int kp0, int g, int t, int m0w, int n0w) {
    const uint32_t* Bh = sB;
    const uint32_t* Bl = sB + 16 * PB2;
    uint32_t bh0[5][2], bl0[5][2], bh1[5][2], bl1[5][2];
    uint32_t ah[2][4], al[2][4];
    loadB(Bh, Bl, 0, bh0, bl0, g, t, n0w);
    loadA32(s_Ah2, s_Al2, kp0, ah, al, g, t, m0w);
    loadB(Bh, Bl, 1, bh1, bl1, g, t, n0w);
    MMA_T5x2(acc, ah, bh0);
    MMA_T5x2(acc, al, bh0);
    MMA_T5x2(acc, ah, bl0);
    loadA32(s_Ah2, s_Al2, kp0 + 8, ah, al, g, t, m0w);
    MMA_T5x2(acc, ah, bh1);
    MMA_T5x2(acc, al, bh1);
    MMA_T5x2(acc, ah, bl1);
}

__device__ __forceinline__ void gemm32(const uint32_t* __restrict__ gW,
                                       const uint32_t* __restrict__ gWnext,
                                       uint32_t* sB0, uint32_t* sB1,
                                       float acc[5][2][4],
                                       const uint32_t* s_Ah2, const uint32_t* s_Al2,
                                       int par0, int tid, int g, int t, int m0w, int n0w) {
#pragma unroll 1
    for (int c = 0; c < 5; ++c) {
        uint32_t* cur = ((par0 + c) & 1) ? sB1 : sB0;
        uint32_t* nxt = ((par0 + c) & 1) ? sB0 : sB1;
        if (c < 4) {
            stage_chunk256(nxt, gW + (size_t)(c + 1) * CHUNK_U32, tid);
            CP_COMMIT(); CP_WAIT1();
        } else if (gWnext) {
            stage_chunk256(nxt, gWnext, tid);
            CP_COMMIT(); CP_WAIT1();
        } else {
            CP_WAIT0();
        }
        __syncthreads();
        mma_chunk32(cur, acc, s_Ah2, s_Al2, c * 16, g, t, m0w, n0w);
        __syncthreads();
    }
}

// 16-row x 40-col chunk (stage B GEMM2, 512 threads)
__device__ __forceinline__ void mma_chunk16(const uint32_t* sB, float acc[5][4],
                                            const uint32_t* Ah, const uint32_t* Al,
                                            int kp0, int g, int t, int m0w, int n0w) {
    const uint32_t* Bh = sB;
    const uint32_t* Bl = sB + 16 * PB2;
    uint32_t bh0[5][2], bl0[5][2], bh1[5][2], bl1[5][2];
    uint32_t ah[4], al[4];
    loadB(Bh, Bl, 0, bh0, bl0, g, t, n0w);
    loadA16(Ah, Al, PA2, kp0, ah, al, g, t, m0w);
    loadB(Bh, Bl, 1, bh1, bl1, g, t, n0w);
    MMA_T5(acc, ah, bh0);
    MMA_T5(acc, al, bh0);
    MMA_T5(acc, ah, bl0);
    loadA16(Ah, Al, PA2, kp0 + 8, ah, al, g, t, m0w);
    MMA_T5(acc, ah, bh1);
    MMA_T5(acc, al, bh1);
    MMA_T5(acc, ah, bl1);
}

__device__ __forceinline__ void gemm16(const uint32_t* __restrict__ gW,
                                       uint32_t* sB0, uint32_t* sB1,
                                       float acc[5][4],
                                       const uint32_t* Ah, const uint32_t* Al,
                                       int tid, int g, int t, int m0w, int n0w) {
#pragma unroll 1
    for (int c = 0; c < 5; ++c) {
        uint32_t* cur = (c & 1) ? sB1 : sB0;
        uint32_t* nxt = (c & 1) ? sB0 : sB1;
        if (c < 4) {
            stage_chunk512(nxt, gW + (size_t)(c + 1) * CHUNK_U32, tid);
            CP_COMMIT(); CP_WAIT1();
        } else {
            CP_WAIT0();
        }
        __syncthreads();
        mma_chunk16(cur, acc, Ah, Al, c * 16, g, t, m0w, n0w);
        __syncthreads();
    }
}

#define ZERO_A524(acc) \
    _Pragma("unroll") for (int f = 0; f < 5; ++f) \
    _Pragma("unroll") for (int mf = 0; mf < 2; ++mf) \
    _Pragma("unroll") for (int r = 0; r < 4; ++r) acc[f][mf][r] = 0.f;
#define ZERO_A54(acc) \
    _Pragma("unroll") for (int f = 0; f < 5; ++f) \
    _Pragma("unroll") for (int r = 0; r < 4; ++r) acc[f][r] = 0.f;
#define ZERO_A64(acc) \
    _Pragma("unroll") for (int f = 0; f < 6; ++f) \
    _Pragma("unroll") for (int r = 0; r < 4; ++r) acc[f][r] = 0.f;

// ===================== stage A: 256 threads, 64-token tile, 2 CTAs/SM =====================
__global__ void __launch_bounds__(256, 2) stageA_mma(
    const float* __restrict__ b1, const float* __restrict__ b2,
    const float* __restrict__ bg, const float* __restrict__ bv,
    const float* __restrict__ lns, const float* __restrict__ lnb)
{
    float* s_bias = smem;                        // 6*160
    float* s_red  = s_bias + 6 * HD;             // 128
    uint32_t* s_Ah2 = (uint32_t*)(s_red + 128);  // [64][84]
    uint32_t* s_Al2 = s_Ah2 + TA * PA2;
    uint32_t* sB0   = s_Al2 + TA * PA2;
    uint32_t* sB1   = sB0 + CHUNK_U32;

    const int v   = blockIdx.x;
    const int n0  = blockIdx.y * TA;
    const int tid = threadIdx.x;
    const int lane = tid & 31;
    const int wid  = tid >> 5;                   // 0..7
    const int g = lane >> 2, t = lane & 3;
    const int m0w = (wid & 1) * 32;
    const int n0w = (wid >> 1) * 40;
    const int pib = n0w / 2;

    const uint32_t* wbase = g_wsplA + (size_t)v * 20 * CHUNK_U32;

    stage_chunk256(sB0, wbase, tid);
    CP_COMMIT();

    for (int l = tid; l < HD; l += 256) {
        s_bias[l]          = b1[v * HD + l];
        s_bias[HD + l]     = b2[v * HD + l];
        s_bias[2*HD + l]   = bg[v * HD + l];
        s_bias[3*HD + l]   = bv[v * HD + l];
        s_bias[4*HD + l]   = lns[v * HD + l];
        s_bias[5*HD + l]   = lnb[v * HD + l];
    }

    // x tile: coalesced from g_embt; split-pack into A buffers
#pragma unroll
    for (int u = 0; u < 20; ++u) {
        int p = u * 256 + tid;                   // 64*80 pairs
        int row = p / 80, pc = p - row * 80;
        float2 xv = *(const float2*)(g_embt + (size_t)(n0 + row) * (HD * NV) + (size_t)v * HD + 2 * pc);
        uint32_t hi, lo;
        splitpack(xv.x, xv.y, hi, lo);
        s_Ah2[row * PA2 + pc] = hi;
        s_Al2[row * PA2 + pc] = lo;
    }
    __syncthreads();

    float acc[5][2][4];

    // GEMM1: h1 = elu(x@W1 + b1)
    ZERO_A524(acc);
    gemm32(wbase, wbase + 5 * CHUNK_U32, sB0, sB1, acc, s_Ah2, s_Al2, 0, tid, g, t, m0w, n0w);
#pragma unroll
    for (int f = 0; f < 5; ++f) {
        int col0 = n0w + f * 8 + 2 * t;
        int pi = pib + f * 4 + t;
#pragma unroll
        for (int mf = 0; mf < 2; ++mf) {
            int r0 = m0w + mf * 16 + g;
            float v00 = eluf(acc[f][mf][0] + s_bias[col0]);
            float v01 = eluf(acc[f][mf][1] + s_bias[col0 + 1]);
            float v10 = eluf(acc[f][mf][2] + s_bias[col0]);
            float v11 = eluf(acc[f][mf][3] + s_bias[col0 + 1]);
            splitpack(v00, v01, s_Ah2[r0 * PA2 + pi], s_Al2[r0 * PA2 + pi]);
            splitpack(v10, v11, s_Ah2[(r0 + 8) * PA2 + pi], s_Al2[(r0 + 8) * PA2 + pi]);
        }
    }

    // GEMM2: h2 = h1@W2 + b2
    ZERO_A524(acc);
    gemm32(wbase + 5 * CHUNK_U32, wbase + 10 * CHUNK_U32, sB0, sB1, acc, s_Ah2, s_Al2, 1, tid, g, t, m0w, n0w);
#pragma unroll
    for (int f = 0; f < 5; ++f) {
        int col0 = n0w + f * 8 + 2 * t;
        int pi = pib + f * 4 + t;
#pragma unroll
        for (int mf = 0; mf < 2; ++mf) {
            int r0 = m0w + mf * 16 + g;
            float v00 = acc[f][mf][0] + s_bias[HD + col0];
            float v01 = acc[f][mf][1] + s_bias[HD + col0 + 1];
            float v10 = acc[f][mf][2] + s_bias[HD + col0];
            float v11 = acc[f][mf][3] + s_bias[HD + col0 + 1];
            splitpack(v00, v01, s_Ah2[r0 * PA2 + pi], s_Al2[r0 * PA2 + pi]);
            splitpack(v10, v11, s_Ah2[(r0 + 8) * PA2 + pi], s_Al2[(r0 + 8) * PA2 + pi]);
        }
    }

    // GEMM3: gate = sigmoid(h2@Wg + bg)
    ZERO_A524(acc);
    gemm32(wbase + 10 * CHUNK_U32, wbase + 15 * CHUNK_U32, sB0, sB1, acc, s_Ah2, s_Al2, 0, tid, g, t, m0w, n0w);
    float gate[5][2][4];
#pragma unroll
    for (int f = 0; f < 5; ++f)
#pragma unroll
        for (int mf = 0; mf < 2; ++mf)
#pragma unroll
            for (int r = 0; r < 4; ++r) {
                int col = n0w + f * 8 + 2 * t + (r & 1);
                gate[f][mf][r] = sigf(acc[f][mf][r] + s_bias[2*HD + col]);
            }

    // GEMM4: y = x + gate*(h2@Wv + bv)  (x re-read from g_embt; y -> packed A)
    ZERO_A524(acc);
    gemm32(wbase + 15 * CHUNK_U32, (const uint32_t*)0, sB0, sB1, acc, s_Ah2, s_Al2, 1, tid, g, t, m0w, n0w);
#pragma unroll
    for (int f = 0; f < 5; ++f) {
        int col0 = n0w + f * 8 + 2 * t;
        int pi = pib + f * 4 + t;
#pragma unroll
        for (int mf = 0; mf < 2; ++mf) {
            int r0 = m0w + mf * 16 + g;
            float2 x0 = *(const float2*)(g_embt + (size_t)(n0 + r0) * (HD * NV) + (size_t)v * HD + col0);
            float2 x1 = *(const float2*)(g_embt + (size_t)(n0 + r0 + 8) * (HD * NV) + (size_t)v * HD + col0);
            float y00 = x0.x + gate[f][mf][0] * (acc[f][mf][0] + s_bias[3*HD + col0]);
            float y01 = x0.y + gate[f][mf][1] * (acc[f][mf][1] + s_bias[3*HD + col0 + 1]);
            float y10 = x1.x + gate[f][mf][2] * (acc[f][mf][2] + s_bias[3*HD + col0]);
            float y11 = x1.y + gate[f][mf][3] * (acc[f][mf][3] + s_bias[3*HD + col0 + 1]);
            splitpack(y00, y01, s_Ah2[r0 * PA2 + pi], s_Al2[r0 * PA2 + pi]);
            splitpack(y10, y11, s_Ah2[(r0 + 8) * PA2 + pi], s_Al2[(r0 + 8) * PA2 + pi]);
        }
    }
    __syncthreads();

    // LayerNorm stats: warp w owns rows 8w..8w+7
#pragma unroll
    for (int rr = 0; rr < 8; ++rr) {
        int row = 8 * wid + rr;
        float s = 0.f, q = 0.f;
#pragma unroll
        for (int u = 0; u < 3; ++u) {
            int pc = u * 32 + lane;
            if (pc < 80) {
                float2 y = unpk(s_Ah2[row * PA2 + pc], s_Al2[row * PA2 + pc]);
                s += y.x + y.y;
                q += y.x * y.x + y.y * y.y;
            }
        }
#pragma unroll
        for (int off = 16; off; off >>= 1) {
            s += __shfl_xor_sync(0xffffffffu, s, off);
            q += __shfl_xor_sync(0xffffffffu, q, off);
        }
        if (lane == 0) {
            float mean = s * (1.f / HD);
            float var  = q * (1.f / HD) - mean * mean;
            s_red[row * 2]     = mean;
            s_red[row * 2 + 1] = rsqrtf(var + 1e-5f);
        }
    }
    __syncthreads();

    // normalized y -> g_trh/g_trl (coalesced)
#pragma unroll
    for (int u = 0; u < 20; ++u) {
        int p = u * 256 + tid;
        int row = p / 80, pc = p - row * 80;
        float mean = s_red[row * 2], rstd = s_red[row * 2 + 1];
        int j0 = 2 * pc, j1 = 2 * pc + 1;
        float2 y = unpk(s_Ah2[row * PA2 + pc], s_Al2[row * PA2 + pc]);
        float y0 = (y.x - mean) * rstd * s_bias[4*HD + j0] + s_bias[5*HD + j0];
        float y1 = (y.y - mean) * rstd * s_bias[4*HD + j1] + s_bias[5*HD + j1];
        uint32_t hi, lo;
        splitpack(y0, y1, hi, lo);
        size_t base = (size_t)(n0 + row) * (NV * 80) + (size_t)v * 80 + pc;
        g_trh[base] = hi;
        g_trl[base] = lo;
    }
}

// ===================== transpose / ctx =====================
__global__ void __launch_bounds__(256) transpose_kernel(const float* __restrict__ emb) {
    __shared__ float s[HD * 17];
    size_t n = blockIdx.x;
    int tid = threadIdx.x;
    const float* src = emb + n * (HD * NV);
    for (int l = tid; l < HD * NV; l += 256) {
        int e = l >> 4, vv = l & 15;
        s[e * 17 + vv] = src[l];
    }
    __syncthreads();
    float* dst = g_embt + n * (HD * NV);
    for (int l = tid; l < HD * NV; l += 256) {
        int vv = l / HD, e = l - vv * HD;
        dst[l] = s[e * 17 + vv];
    }
}

__global__ void ctx_kernel(const float* __restrict__ ac, const float* __restrict__ Wc) {
    int b = blockIdx.x, j = threadIdx.x;
    float s = 0.f;
    for (int k = 0; k < HD; ++k)
        s = fmaf(ac[b * HD + k], Wc[k * HD + j], s);
    g_ctx[b * HD + j] = s;
}

// ===================== stage B: 512 threads, 64-token tile (R8-proven) =====================
__device__ __forceinline__ void stageB_chunk(uint32_t* dAh, uint32_t* dAl, uint32_t* dB,
                                             int n0, int c, int tid) {
    if (tid < 256) {
        int r = tid >> 2, q = tid & 3;
        size_t abase = (size_t)(n0 + r) * (NV * 80) + (size_t)c * 16 + q * 4;
        cp16(smem_u32(dAh + r * PAB + q * 4), g_trh + abase);
    } else {
        int t2 = tid - 256;
        int r = t2 >> 2, q = t2 & 3;
        size_t abase = (size_t)(n0 + r) * (NV * 80) + (size_t)c * 16 + q * 4;
        cp16(smem_u32(dAl + r * PAB + q * 4), g_trl + abase);
    }
    const uint32_t* gsrc = g_wsplB1 + (size_t)c * CHUNKB;
    uint32_t db = smem_u32(dB);
#pragma unroll
    for (int i = 0; i < 4; ++i) {
        int idx = i * 512 + tid;
        if (idx < 1600) cp16(db + idx * 16, gsrc + idx * 4);
    }
}

__device__ __forceinline__ void mma_chunkB(const uint32_t* A_h, const uint32_t* A_l,
                                           const uint32_t* B, float acc[6][4],
                                           int g, int t, int m0w, int n0w48) {
    const uint32_t* Bh = B;
    const uint32_t* Bl = B + 16 * PBB;
#pragma unroll
    for (int s = 0; s < 2; ++s) {
        int kp = s * 8;
        uint32_t ah[4], al[4], bh[6][2], bl[6][2];
        loadA16(A_h, A_l, PAB, kp, ah, al, g, t, m0w);
#pragma unroll
        for (int f = 0; f < 6; ++f) {
            int nn = n0w48 + f * 8 + g;
            bh[f][0] = Bh[(kp + t) * PBB + nn]; bh[f][1] = Bh[(kp + 4 + t) * PBB + nn];
            bl[f][0] = Bl[(kp + t) * PBB + nn]; bl[f][1] = Bl[(kp + 4 + t) * PBB + nn];
        }
        MMA_T6(acc, ah, bh);
        MMA_T6(acc, al, bh);
        MMA_T6(acc, ah, bl);
    }
}

__global__ void __launch_bounds__(512, 1) stageB_mma(
    const float* __restrict__ b1,  const float* __restrict__ b2,
    const float* __restrict__ bsk, const float* __restrict__ bg,
    const float* __restrict__ bv,  const float* __restrict__ lns,
    const float* __restrict__ lnb, const float* __restrict__ Wg,
    const float* __restrict__ Wv,
    float* __restrict__ out_sw, float* __restrict__ out_sg)
{
    uint32_t* sm   = (uint32_t*)smem;
    uint32_t* bufr = sm;                       // 17920 u32 union region
    uint32_t* s_Ah2 = sm + 17920;              // [64][84]
    uint32_t* s_Al2 = s_Ah2 + TA * PA2;
    float* s_h3 = (float*)(s_Al2 + TA * PA2);  // [160][65]
    float* s_sk = s_h3 + 160 * 65;             // [64][16]
    float* s_gv = s_sk + TA * NV;              // [160][32]
    float* s_cb = s_gv + HD * 32;              // 400

    uint32_t* sAh[2] = { bufr,        bufr + 2560 };
    uint32_t* sAl[2] = { bufr + 1280, bufr + 3840 };
    uint32_t* sBB[2] = { bufr + 5120, bufr + 5120 + CHUNKB };
    uint32_t* sB20 = bufr;
    uint32_t* sB21 = bufr + CHUNK_U32;

    const int n0  = blockIdx.x * TA;
    const int tid = threadIdx.x;
    const int lane = tid & 31;
    const int wid  = tid >> 5;                 // 0..15
    const int g = lane >> 2, t = lane & 3;
    const int m0w16 = (wid & 3) * 16;
    const int n0w48 = (wid >> 2) * 48;
    const int n0w40 = (wid >> 2) * 40;
    const int bidx  = n0 >> 9;

    stageB_chunk(sAh[0], sAl[0], sBB[0], n0, 0, tid);
    CP_COMMIT();

    if (tid < HD) {
        s_cb[tid]       = b1[tid] + g_ctx[bidx * HD + tid];
        s_cb[HD + tid]  = b2[tid];
    }
    if (tid < NV) {
        s_cb[320 + tid] = bg[tid];
        s_cb[336 + tid] = bv[tid];
        s_cb[352 + tid] = lns[tid];
        s_cb[368 + tid] = lnb[tid];
        s_cb[384 + tid] = bsk[tid];
    }
#pragma unroll
    for (int u = 0; u < 10; ++u) {
        int l = u * 512 + tid;
        int cc = l & 31, k = l >> 5;
        s_gv[k * 32 + cc] = (cc < NV) ? Wg[k * NV + cc] : Wv[k * NV + (cc - NV)];
    }

    float acc[6][4];
    ZERO_A64(acc);

#pragma unroll 1
    for (int c = 0; c < 80; ++c) {
        int cur = c & 1, nxt = cur ^ 1;
        if (c < 79) {
            stageB_chunk(sAh[nxt], sAl[nxt], sBB[nxt], n0, c + 1, tid);
            CP_COMMIT(); CP_WAIT1();
        } else {
            CP_WAIT0();
        }
        __syncthreads();
        mma_chunkB(sAh[cur], sAl[cur], sBB[cur], acc, g, t, m0w16, n0w48);
        __syncthreads();
    }

#pragma unroll
    for (int f = 0; f < 6; ++f) {
        int col0 = n0w48 + f * 8 + 2 * t;
        int r0 = m0w16 + g;
        float v00 = acc[f][0], v01 = acc[f][1];
        float v10 = acc[f][2], v11 = acc[f][3];
        if (col0 < HD) {
            int pi = col0 >> 1;
            float e00 = eluf(v00 + s_cb[col0]);
            float e01 = eluf(v01 + s_cb[col0 + 1]);
            float e10 = eluf(v10 + s_cb[col0]);
            float e11 = eluf(v11 + s_cb[col0 + 1]);
            splitpack(e00, e01, s_Ah2[r0 * PA2 + pi], s_Al2[r0 * PA2 + pi]);
            splitpack(e10, e11, s_Ah2[(r0 + 8) * PA2 + pi], s_Al2[(r0 + 8) * PA2 + pi]);
        } else if (col0 < HD + NV) {
            int sc = col0 - HD;
            s_sk[r0 * NV + sc]           = v00;
            s_sk[r0 * NV + sc + 1]       = v01;
            s_sk[(r0 + 8) * NV + sc]     = v10;
            s_sk[(r0 + 8) * NV + sc + 1] = v11;
        }
    }
    __syncthreads();

    stage_chunk512(sB20, g_wsplB2, tid);
    CP_COMMIT();

    float acc5[5][4];
    ZERO_A54(acc5);
    gemm16(g_wsplB2, sB20, sB21, acc5, s_Ah2, s_Al2, tid, g, t, m0w16, n0w40);
#pragma unroll
    for (int f = 0; f < 5; ++f)
#pragma unroll
        for (int r = 0; r < 4; ++r) {
            int row = m0w16 + g + (r >> 1) * 8;
            int col = n0w40 + f * 8 + 2 * t + (r & 1);
            s_h3[col * 65 + row] = acc5[f][r] + s_cb[HD + col];
        }
    __syncthreads();

    float gv[4] = {0.f, 0.f, 0.f, 0.f};
    const int c = lane;
#pragma unroll 4
    for (int k = 0; k < HD; ++k) {
        float w = s_gv[k * 32 + c];
        const float* h3k = s_h3 + k * 65 + 4 * wid;
#pragma unroll
        for (int rr = 0; rr < 4; ++rr)
            gv[rr] = fmaf(h3k[rr], w, gv[rr]);
    }

    int vc = c & 15;
    float bgv = (c < NV) ? s_cb[320 + vc] : s_cb[336 + vc];
    float skb = s_cb[384 + vc];
    float lsc = s_cb[352 + vc], lbc = s_cb[368 + vc];
#pragma unroll
    for (int rr = 0; rr < 4; ++rr) {
        int row = 4 * wid + rr;
        float z = gv[rr] + bgv;
        float gval = (c < NV) ? sigf(z) : z;
        float partner = __shfl_xor_sync(0xffffffffu, gval, 16);
        float y = s_sk[row * NV + vc] + skb + gval * partner;
        float s = y, q = y * y;
#pragma unroll
        for (int off = 8; off; off >>= 1) {
            s += __shfl_xor_sync(0xffffffffu, s, off);
            q += __shfl_xor_sync(0xffffffffu, q, off);
        }
        float mean = s * (1.f / 16.f);
        float var  = q * (1.f / 16.f) - mean * mean;
        float rstd = rsqrtf(var + 1e-5f);
        float logit = (y - mean) * rstd * lsc + lbc;
        float mx = logit;
#pragma unroll
        for (int off = 8; off; off >>= 1)
            mx = fmaxf(mx, __shfl_xor_sync(0xffffffffu, mx, off));
        float e = expf(logit - mx);
        float se = e;
#pragma unroll
        for (int off = 8; off; off >>= 1)
            se += __shfl_xor_sync(0xffffffffu, se, off);
        if (c < NV) {
            int n = n0 + row;
            out_sw[(size_t)n * NV + c] = e / se;
            out_sg[(size_t)n * NV + c] = gval;
        }
    }
}

// ===================== stage C =====================
__global__ void __launch_bounds__(256) stageC_kernel(const float* __restrict__ sw,
                                                     float* __restrict__ out_tc) {
    __shared__ float s_w[16 * NV];
    int n0 = blockIdx.x * 16;
    int tid = threadIdx.x;
    s_w[tid] = sw[(size_t)n0 * NV + tid];
    __syncthreads();
#pragma unroll
    for (int u = 0; u < 5; ++u) {
        int l = u * 256 + tid;
        int m = l / 80, pc = l - m * 80;
        size_t base = (size_t)(n0 + m) * (NV * 80) + pc;
        float a0 = 0.f, a1 = 0.f;
#pragma unroll
        for (int vv = 0; vv < NV; ++vv) {
            float2 x = unpk(g_trh[base + vv * 80], g_trl[base + vv * 80]);
            float w = s_w[m * NV + vv];
            a0 = fmaf(x.x, w, a0);
            a1 = fmaf(x.y, w, a1);
        }
        float* dst = out_tc + (size_t)(n0 + m) * HD + 2 * pc;
        dst[0] = a0;
        dst[1] = a1;
    }
}

// ===================== launch =====================
extern "C" void kernel_launch(void* const* d_in, const int* in_sizes, int n_in,
                              void* d_out, int out_size)
{
    const float* emb   = (const float*)d_in[0];
    const float* ac    = (const float*)d_in[1];
    const float* sv_W1 = (const float*)d_in[2];
    const float* sv_b1 = (const float*)d_in[3];
    const float* sv_W2 = (const float*)d_in[4];
    const float* sv_b2 = (const float*)d_in[5];
    const float* sv_Wg = (const float*)d_in[6];
    const float* sv_bg = (const float*)d_in[7];
    const float* sv_Wv = (const float*)d_in[8];
    const float* sv_bv = (const float*)d_in[9];
    const float* sv_ls = (const float*)d_in[10];
    const float* sv_lb = (const float*)d_in[11];
    const float* fWsk  = (const float*)d_in[12];
    const float* fbsk  = (const float*)d_in[13];
    const float* fW1   = (const float*)d_in[14];
    const float* fb1   = (const float*)d_in[15];
    const float* fWc   = (const float*)d_in[16];
    const float* fW2   = (const float*)d_in[17];
    const float* fb2   = (const float*)d_in[18];
    const float* fWg   = (const float*)d_in[19];
    const float* fbg   = (const float*)d_in[20];
    const float* fWv   = (const float*)d_in[21];
    const float* fbv   = (const float*)d_in[22];
    const float* fls   = (const float*)d_in[23];
    const float* flb   = (const float*)d_in[24];

    float* out    = (float*)d_out;
    float* out_tc = out;
    float* out_sw = out + (size_t)NTOK * HD;
    float* out_sg = out_sw + (size_t)NTOK * NV;

    const int SMEM_A = (6 * HD + 128) * 4 + (2 * TA * PA2 + 2 * CHUNK_U32) * 4;   // 90,368 (2 CTAs/SM)
    const int SMEM_B = (17920 + 2 * TA * PA2) * 4 + (160 * 65 + TA * NV + HD * 32 + 400) * 4;
    cudaFuncSetAttribute(stageA_mma, cudaFuncAttributeMaxDynamicSharedMemorySize, SMEM_A);
    cudaFuncSetAttribute(stageB_mma, cudaFuncAttributeMaxDynamicSharedMemorySize, SMEM_B);

    prepA_kernel<<<320, 256>>>(sv_W1, sv_W2, sv_Wg, sv_Wv);
    prepB1_kernel<<<80, 256>>>(fW1, fWsk);
    prepB2_kernel<<<5, 256>>>(fW2);
    ctx_kernel<<<64, HD>>>(ac, fWc);
    transpose_kernel<<<NTOK, 256>>>(emb);
    stageA_mma<<<dim3(NV, NTOK / TA), 256, SMEM_A>>>(sv_b1, sv_b2, sv_bg, sv_bv, sv_ls, sv_lb);
    stageB_mma<<<NTOK / TA, 512, SMEM_B>>>(fb1, fb2, fbsk, fbg, fbv, fls, flb,
                                           fWg, fWv, out_sw, out_sg);
    stageC_kernel<<<NTOK / 16, 256>>>(out_sw, out_tc);
}